// round 8
// baseline (speedup 1.0000x reference)
#include <cuda_runtime.h>

// Persistent neural-CDE kernel. 128 CTAs x 1024 threads (32 warps/SM, 50% occ).
// CTA r owns batch row r (gemv/RK4) and W3 column-slice h=r (GEMM).
// W1/W2/dup-W3 resident in smem. Direct all-poll flag barrier (no hub hop).
// GEMM: 2 rows x 2 cols per thread, flat K=128, FFMA2 natural pairs.

#define NCTAS 128
#define NT    1024

typedef unsigned long long u64;

__device__ float g_h2T[128 * 128];     // [k][r]
__device__ float g_dz [128 * 128];     // [b][h]
__device__ float g_dx [128 * 3 * 32];  // [b][sel][c]
__device__ unsigned int g_slot[128 * 8];  // per-CTA arrival counters, 32B stride

// Direct all-poll barrier: arrive with release store to own slot; warp 0 of
// EVERY CTA polls all 128 slots for >= target (producers may already be a
// barrier ahead). Monotonic counters -> graph-replay safe.
__device__ __forceinline__ void grid_barrier(unsigned int target)
{
    __syncthreads();
    if (threadIdx.x < 32) {
        const int lane = threadIdx.x;
        if (lane == 0) {
            __threadfence();
            asm volatile("st.release.gpu.b32 [%0], %1;"
                         :: "l"(g_slot + blockIdx.x * 8), "r"(target) : "memory");
        }
        const unsigned int* p0 = g_slot + (lane * 4 + 0) * 8;
        const unsigned int* p1 = g_slot + (lane * 4 + 1) * 8;
        const unsigned int* p2 = g_slot + (lane * 4 + 2) * 8;
        const unsigned int* p3 = g_slot + (lane * 4 + 3) * 8;
        bool ok;
        do {
            unsigned int a, b, c, d;
            asm volatile("ld.relaxed.gpu.b32 %0, [%1];" : "=r"(a) : "l"(p0) : "memory");
            asm volatile("ld.relaxed.gpu.b32 %0, [%1];" : "=r"(b) : "l"(p1) : "memory");
            asm volatile("ld.relaxed.gpu.b32 %0, [%1];" : "=r"(c) : "l"(p2) : "memory");
            asm volatile("ld.relaxed.gpu.b32 %0, [%1];" : "=r"(d) : "l"(p3) : "memory");
            ok = ((int)(a - target) >= 0) && ((int)(b - target) >= 0) &&
                 ((int)(c - target) >= 0) && ((int)(d - target) >= 0);
        } while (!__all_sync(0xffffffffu, ok));
        asm volatile("fence.acq_rel.gpu;" ::: "memory");
    }
    __syncthreads();
}

// GEMV: out[j] = relu(b[j] + sum_k v[k]*W[k][j]); operands in smem.
// 1024 threads: 32 j-quads x 32 k-chunks of 4.
__device__ __forceinline__ void gemv128(const float* __restrict__ vs,
                                        const float* __restrict__ Wsm,
                                        const float* __restrict__ bsm,
                                        float* __restrict__ outv,
                                        float* __restrict__ sp)
{
    const int tid = threadIdx.x;
    const int j0 = (tid & 31) << 2, kc = tid >> 5;   // kc 0..31
    const int k0 = kc << 2;
    float4 vv = *(const float4*)(vs + k0);
    float4 acc = make_float4(0.f, 0.f, 0.f, 0.f);
    const float* wb = Wsm + k0 * 128 + j0;
    #define GSTEP(VK, KK) { float4 w4 = *(const float4*)(wb + (KK) * 128); \
        acc.x = fmaf(VK, w4.x, acc.x); acc.y = fmaf(VK, w4.y, acc.y);     \
        acc.z = fmaf(VK, w4.z, acc.z); acc.w = fmaf(VK, w4.w, acc.w); }
    GSTEP(vv.x, 0) GSTEP(vv.y, 1) GSTEP(vv.z, 2) GSTEP(vv.w, 3)
    #undef GSTEP
    *(float4*)(sp + kc * 128 + j0) = acc;
    __syncthreads();
    if (tid < 128) {
        float s = bsm[tid];
        #pragma unroll
        for (int q = 0; q < 32; q++)
            s += sp[q * 128 + tid];
        outv[tid] = fmaxf(s, 0.0f);
    }
    __syncthreads();
}

// cephes-style rational tanh: returns p, writes q; tanh(x) = p/q. FMA-only.
__device__ __forceinline__ float tanh_pq(float x, float& qo)
{
    x = fminf(fmaxf(x, -7.90531110591164f), 7.90531110591164f);
    float x2 = x * x;
    float p = fmaf(x2, -2.76076847742355e-16f, 2.00018790482477e-13f);
    p = fmaf(p, x2, -8.60467152213735e-11f);
    p = fmaf(p, x2,  5.12229709037114e-08f);
    p = fmaf(p, x2,  1.48572235717979e-05f);
    p = fmaf(p, x2,  6.37261928875436e-04f);
    p = fmaf(p, x2,  4.89352455891786e-03f);
    p = p * x;
    float q = fmaf(x2, 1.19825839466702e-06f, 1.18534705686654e-04f);
    q = fmaf(q, x2, 2.26843463243900e-03f);
    qo = fmaf(q, x2, 4.89352518554385e-03f);
    return p;
}

__device__ __forceinline__ void rcp4(const float* q, float* inv)
{
    float a01 = q[0] * q[1], a23 = q[2] * q[3], P = a01 * a23, R;
    asm("rcp.approx.f32 %0, %1;" : "=f"(R) : "f"(P));
    inv[0] = R * q[1] * a23;
    inv[1] = R * q[0] * a23;
    inv[2] = R * a01 * q[3];
    inv[3] = R * a01 * q[2];
}

// smem (floats): h2s 16384 | w1s 16384 | w2s 16384 | w3d 8192 |
//                b1s 128 | b2s 128 | ys 128 | zs 128 | kacc 128 | misc 16
// sp (4096) / h1s / h2row alias the dead front of h2s.
#define SMEM_FLOATS (16384*3 + 8192 + 5*128 + 16)
#define SMEM_BYTES  (SMEM_FLOATS * 4)

extern __shared__ float smem[];

__global__ __launch_bounds__(NT, 1)
void cde_kernel(const float* __restrict__ coeffs,
                const float* __restrict__ W1, const float* __restrict__ b1,
                const float* __restrict__ W2, const float* __restrict__ b2,
                const float* __restrict__ W3, const float* __restrict__ b3,
                const float* __restrict__ Wi, const float* __restrict__ bi,
                const float* __restrict__ Wr, const float* __restrict__ br,
                float* __restrict__ out)
{
    float* h2s   = smem;                // [k][b] 128x128
    float* w1s   = h2s  + 16384;        // [k][j]
    float* w2s   = w1s  + 16384;
    float* w3d   = w2s  + 16384;        // [k][2c dup] 128x64
    float* b1s   = w3d  + 8192;
    float* b2s   = b1s  + 128;
    float* ys    = b2s  + 128;
    float* zs    = ys   + 128;
    float* kacc  = zs   + 128;
    unsigned int* sbase = (unsigned int*)(kacc + 128);
    float* sp    = h2s;                 // aliases (dead before h2s staging)
    float* h1s   = h2s + 4096;
    float* h2row = h2s + 4224;

    const int tid = threadIdx.x;
    const int r   = blockIdx.x;         // owned batch row == owned h-slice

    if (tid == 0) {
        unsigned int g0;
        asm volatile("ld.relaxed.gpu.b32 %0, [%1];"
                     : "=r"(g0) : "l"(g_slot + blockIdx.x * 8));
        *sbase = g0;
    }

    // ---- prologue: stage weights ----
    #pragma unroll
    for (int i = 0; i < 4; i++) {
        int idx = tid + i * NT;         // 4096 float4 per matrix
        ((float4*)w1s)[idx] = ((const float4*)W1)[idx];
        ((float4*)w2s)[idx] = ((const float4*)W2)[idx];
    }
    #pragma unroll
    for (int i = 0; i < 4; i++) {       // dup-W3 slice: 4096 float2
        int idx = tid + i * NT;
        int k = idx >> 5, c = idx & 31;
        float w = W3[k * 4096 + r * 32 + c];
        *(float2*)(w3d + k * 64 + 2 * c) = make_float2(w, w);
    }
    if (tid < 128) { b1s[tid] = b1[tid]; b2s[tid] = b2[tid]; }

    // z0 = X(0) @ Wi + bi
    if (tid < 128) {
        const float* ca = coeffs + (size_t)r * 8192;
        float acc = bi[tid];
        #pragma unroll
        for (int c = 0; c < 32; c++)
            acc = fmaf(ca[c], Wi[c * 128 + tid], acc);
        zs[tid] = acc; ys[tid] = acc; kacc[tid] = 0.0f;
    }
    __syncthreads();

    const unsigned int base = *sbase;
    unsigned int bno = 0;

    // ---- GEMM mapping: 64 row-pairs x 16 col-pairs ----
    const int rp = tid >> 4, cp = tid & 15;
    const int r0 = rp << 1, c0 = cp << 1;
    unsigned int ha0, wa0;
    {
        u64 t = __cvta_generic_to_shared(h2s + r0);
        ha0 = (unsigned int)t;
        t = __cvta_generic_to_shared(w3d + (cp << 2));
        wa0 = (unsigned int)t;
    }
    const float2 b3v = *(const float2*)(b3 + r * 32 + c0);
    u64 Bc0, Bc1;
    asm("mov.b64 %0, {%1,%1};" : "=l"(Bc0) : "f"(b3v.x));
    asm("mov.b64 %0, {%1,%1};" : "=l"(Bc1) : "f"(b3v.y));

    for (int s = 0; s < 64; s++) {
        // publish dX for this segment (f=0, f=0.5, f=1)
        if (tid < 32) {
            const float* bc = coeffs + (size_t)r * 8192 + s * 128;
            int c = tid;
            float cb = bc[32 + c], c2 = bc[64 + c], c3 = bc[96 + c];
            g_dx[(r * 3 + 0) * 32 + c] = cb;
            g_dx[(r * 3 + 1) * 32 + c] = fmaf(0.25f, c3, fmaf(0.5f, c2, cb));
            g_dx[(r * 3 + 2) * 32 + c] = (s < 63) ? bc[128 + 32 + c]
                                                  : (cb + c2 + c3);
        }

        for (int stage = 0; stage < 4; stage++) {
            // ---- row-owner: layers 1,2 on own row, publish h2 ----
            gemv128(ys,  w1s, b1s, h1s,   sp);
            gemv128(h1s, w2s, b2s, h2row, sp);
            if (tid < 128)
                g_h2T[tid * 128 + r] = h2row[tid];

            grid_barrier(base + (++bno));   // A: all h2 rows + dX published

            // prefetch dX for the contraction (hides L2 under the GEMM)
            const int sel = (stage == 0) ? 0 : ((stage == 3) ? 2 : 1);
            float2 d0 = *(const float2*)(g_dx + (r0 * 3 + sel) * 32 + c0);
            float2 d1 = *(const float2*)(g_dx + ((r0 + 1) * 3 + sel) * 32 + c0);

            // ---- stage h2T into smem ----
            #pragma unroll
            for (int i = 0; i < 4; i++)
                ((float4*)h2s)[tid + i * NT] = ((const float4*)g_h2T)[tid + i * NT];
            __syncthreads();

            // ---- GEMM: 2 rows x 2 cols per thread, K=128, FFMA2 ----
            u64 C0 = Bc0, C1 = Bc1;     // (r0,r0+1 | c0), (r0,r0+1 | c1)
            {
                unsigned int hp = ha0, wp = wa0;
                #define MSTEP(KK)                                                    \
                {   u64 h01, wd0, wd1;                                               \
                    asm volatile("ld.shared.b64 %0,[%1+%2];"                          \
                        : "=l"(h01) : "r"(hp), "n"((KK)*512) : "memory");             \
                    asm volatile("ld.shared.v2.b64 {%0,%1},[%2+%3];"                  \
                        : "=l"(wd0), "=l"(wd1) : "r"(wp), "n"((KK)*256) : "memory");  \
                    asm("fma.rn.f32x2 %0,%1,%2,%0;" : "+l"(C0) : "l"(h01), "l"(wd0)); \
                    asm("fma.rn.f32x2 %0,%1,%2,%0;" : "+l"(C1) : "l"(h01), "l"(wd1)); }
                #pragma unroll 1
                for (int k8 = 0; k8 < 16; k8++) {
                    MSTEP(0) MSTEP(1) MSTEP(2) MSTEP(3)
                    MSTEP(4) MSTEP(5) MSTEP(6) MSTEP(7)
                    hp += 8 * 512; wp += 8 * 256;
                }
                #undef MSTEP
            }
            float x0, x1, x2, x3;       // x0=out[r0][c0] x1=out[r0+1][c0]
            asm("mov.b64 {%0,%1}, %2;" : "=f"(x0), "=f"(x1) : "l"(C0));
            asm("mov.b64 {%0,%1}, %2;" : "=f"(x2), "=f"(x3) : "l"(C1));

            // ---- tanh + contraction with dX ----
            float p[4], q[4], inv[4];
            p[0] = tanh_pq(x0, q[0]); p[1] = tanh_pq(x1, q[1]);
            p[2] = tanh_pq(x2, q[2]); p[3] = tanh_pq(x3, q[3]);
            rcp4(q, inv);

            float pr0 = p[0] * inv[0] * d0.x + p[2] * inv[2] * d0.y;  // row r0
            float pr1 = p[1] * inv[1] * d1.x + p[3] * inv[3] * d1.y;  // row r0+1
            #pragma unroll
            for (int off = 8; off >= 1; off >>= 1) {
                pr0 += __shfl_down_sync(0xffffffffu, pr0, off);
                pr1 += __shfl_down_sync(0xffffffffu, pr1, off);
            }
            if (cp == 0) {              // lanes 0 and 16 of each warp
                g_dz[ r0      * 128 + r] = pr0;
                g_dz[(r0 + 1) * 128 + r] = pr1;
            }

            grid_barrier(base + (++bno));   // B: dz complete

            // ---- row-owner: RK4 stage update ----
            if (tid < 128) {
                int h = tid;
                float dz = g_dz[r * 128 + h];
                float kv = kacc[h];
                float zq = zs[h];
                float kw = (stage == 0 || stage == 3) ? 1.0f : 2.0f;
                kv = fmaf(kw, dz, kv);
                if (stage < 3) {
                    float aa = (stage == 2) ? 1.0f : 0.5f;
                    ys[h] = fmaf(aa, dz, zq);
                    kacc[h] = kv;
                } else {
                    float zn = fmaf(1.0f / 6.0f, kv, zq);
                    zs[h] = zn;
                    ys[h] = zn;
                    kacc[h] = 0.0f;
                }
            }
            __syncthreads();
        }
    }

    // ---- readout: out[r] = sigmoid(z @ Wr + br) ----
    if (tid < 32) {
        float part = 0.0f;
        #pragma unroll
        for (int h = tid; h < 128; h += 32)
            part = fmaf(zs[h], Wr[h], part);
        #pragma unroll
        for (int off = 16; off >= 1; off >>= 1)
            part += __shfl_down_sync(0xffffffffu, part, off);
        if (tid == 0)
            out[r] = 1.0f / (1.0f + __expf(-(part + br[0])));
    }
}

extern "C" void kernel_launch(void* const* d_in, const int* in_sizes, int n_in,
                              void* d_out, int out_size)
{
    const float* coeffs = (const float*)d_in[0];
    const float* W1 = (const float*)d_in[1];
    const float* b1 = (const float*)d_in[2];
    const float* W2 = (const float*)d_in[3];
    const float* b2 = (const float*)d_in[4];
    const float* W3 = (const float*)d_in[5];
    const float* b3 = (const float*)d_in[6];
    const float* Wi = (const float*)d_in[7];
    const float* bi = (const float*)d_in[8];
    const float* Wr = (const float*)d_in[9];
    const float* br = (const float*)d_in[10];
    float* out = (float*)d_out;

    cudaFuncSetAttribute(cde_kernel,
                         cudaFuncAttributeMaxDynamicSharedMemorySize, SMEM_BYTES);
    cde_kernel<<<NCTAS, NT, SMEM_BYTES>>>(coeffs, W1, b1, W2, b2, W3, b3,
                                          Wi, bi, Wr, br, out);
}

// round 9
// speedup vs baseline: 1.7377x; 1.7377x over previous
#include <cuda_runtime.h>

// Persistent neural-CDE kernel. 128 CTAs x 512 threads. CTA r owns batch row
// r (gemv/RK4) and W3 column-slice h=r (GEMM). W1/W2/W3-slice in smem.
// Champion (R3) structure; change: h2T is NOT staged to smem — the GEMM
// streams it from global with register double-buffering (coalesced 32B
// sectors per warp), removing the staging phase from the critical path.

#define NCTAS 128
#define NT    512

typedef unsigned long long u64;

__device__ float g_h2T[128 * 128];    // [k][r]
__device__ float g_dz [128 * 128];    // [b][h]
__device__ float g_dx [128 * 3 * 32]; // [b][sel][c]
__device__ unsigned int g_slot[128];  // per-CTA arrival counters (monotonic)
__device__ unsigned int g_gen;        // barrier generation (monotonic)

__device__ __forceinline__ void grid_barrier(unsigned int target)
{
    __syncthreads();
    if (blockIdx.x == 0) {
        if (threadIdx.x < 32) {
            if (threadIdx.x == 0) {
                __threadfence();   // release our CTA's writes (gpu scope)
                asm volatile("st.release.gpu.b32 [%0], %1;"
                             :: "l"(g_slot), "r"(target) : "memory");
            }
            const unsigned int* p = g_slot + threadIdx.x * 4;
            unsigned int a, b, c, d; bool ok;
            do {
                asm volatile("ld.relaxed.gpu.v4.b32 {%0,%1,%2,%3}, [%4];"
                             : "=r"(a), "=r"(b), "=r"(c), "=r"(d)
                             : "l"(p) : "memory");
                ok = (a == target) && (b == target) && (c == target) && (d == target);
            } while (!__all_sync(0xffffffffu, ok));
            if (threadIdx.x == 0) {
                asm volatile("fence.acq_rel.gpu;" ::: "memory");
                asm volatile("st.relaxed.gpu.b32 [%0], %1;"
                             :: "l"(&g_gen), "r"(target) : "memory");
            }
        }
    } else {
        if (threadIdx.x == 0) {
            __threadfence();
            asm volatile("st.release.gpu.b32 [%0], %1;"
                         :: "l"(g_slot + blockIdx.x), "r"(target) : "memory");
            unsigned int g;
            do {
                asm volatile("ld.acquire.gpu.b32 %0, [%1];"
                             : "=r"(g) : "l"(&g_gen) : "memory");
            } while (g != target);
        }
    }
    __syncthreads();
}

// GEMV: out[j] = relu(b[j] + sum_k v[k]*W[k][j]); all operands in smem.
// 512 threads: j = tid&127, 4-way k split.
__device__ __forceinline__ void gemv128(const float* __restrict__ vs,
                                        const float* __restrict__ Wsm,
                                        const float* __restrict__ bsm,
                                        float* __restrict__ outv,
                                        float* __restrict__ sp)
{
    const int tid = threadIdx.x;
    const int j = tid & 127, kq = tid >> 7;
    const float* w = Wsm + (kq << 5) * 128 + j;
    const float* v = vs + (kq << 5);
    float acc0 = 0.f, acc1 = 0.f;
    #pragma unroll
    for (int k = 0; k < 32; k += 2) {
        acc0 = fmaf(v[k],     w[ k      * 128], acc0);
        acc1 = fmaf(v[k + 1], w[(k + 1) * 128], acc1);
    }
    sp[(kq << 7) + j] = acc0 + acc1;
    __syncthreads();
    if (tid < 128) {
        float s = bsm[tid] + sp[tid] + sp[128 + tid] + sp[256 + tid] + sp[384 + tid];
        outv[tid] = fmaxf(s, 0.0f);
    }
    __syncthreads();
}

// cephes-style rational tanh: returns p, writes q; tanh(x) = p/q. FMA-only.
__device__ __forceinline__ float tanh_pq(float x, float& qo)
{
    x = fminf(fmaxf(x, -7.90531110591164f), 7.90531110591164f);
    float x2 = x * x;
    float p = fmaf(x2, -2.76076847742355e-16f, 2.00018790482477e-13f);
    p = fmaf(p, x2, -8.60467152213735e-11f);
    p = fmaf(p, x2,  5.12229709037114e-08f);
    p = fmaf(p, x2,  1.48572235717979e-05f);
    p = fmaf(p, x2,  6.37261928875436e-04f);
    p = fmaf(p, x2,  4.89352455891786e-03f);
    p = p * x;
    float q = fmaf(x2, 1.19825839466702e-06f, 1.18534705686654e-04f);
    q = fmaf(q, x2, 2.26843463243900e-03f);
    qo = fmaf(q, x2, 4.89352518554385e-03f);
    return p;
}

// batched reciprocal: 1 MUFU per 4 divisions
__device__ __forceinline__ void rcp4(const float* q, float* inv)
{
    float a01 = q[0] * q[1], a23 = q[2] * q[3], P = a01 * a23, R;
    asm("rcp.approx.f32 %0, %1;" : "=f"(R) : "f"(P));
    inv[0] = R * q[1] * a23;
    inv[1] = R * q[0] * a23;
    inv[2] = R * a01 * q[3];
    inv[3] = R * a01 * q[2];
}

// smem (floats): w1s 16384 | w2s 16384 | w3s 4096 | sp 512 |
//                b1s 128 | b2s 128 | ys 128 | zs 128 | kacc 128 |
//                h1s 128 | h2row 128 | misc 16     (no h2 staging buffer)
#define SMEM_FLOATS (16384*2 + 4096 + 512 + 7*128 + 16)
#define SMEM_BYTES  (SMEM_FLOATS * 4)

extern __shared__ float smem[];

__global__ __launch_bounds__(NT, 1)
void cde_kernel(const float* __restrict__ coeffs,
                const float* __restrict__ W1, const float* __restrict__ b1,
                const float* __restrict__ W2, const float* __restrict__ b2,
                const float* __restrict__ W3, const float* __restrict__ b3,
                const float* __restrict__ Wi, const float* __restrict__ bi,
                const float* __restrict__ Wr, const float* __restrict__ br,
                float* __restrict__ out)
{
    float* w1s   = smem;                // [k][j]
    float* w2s   = w1s  + 16384;
    float* w3s   = w2s  + 16384;        // [k][c] 128x32 (our h's slice)
    float* sp    = w3s  + 4096;
    float* b1s   = sp   + 512;
    float* b2s   = b1s  + 128;
    float* ys    = b2s  + 128;
    float* zs    = ys   + 128;
    float* kacc  = zs   + 128;
    float* h1s   = kacc + 128;
    float* h2row = h1s  + 128;
    unsigned int* sbase = (unsigned int*)(h2row + 128);

    const int tid = threadIdx.x;
    const int r   = blockIdx.x;         // owned batch row == owned h-slice

    // barrier base (monotonic across graph replays); stable at launch start
    if (tid == 0) {
        unsigned int g0;
        asm volatile("ld.relaxed.gpu.b32 %0, [%1];" : "=r"(g0) : "l"(&g_gen));
        *sbase = g0;
    }

    // ---- prologue: stage weights into smem ----
    #pragma unroll
    for (int i = 0; i < 8; i++) {
        int idx = tid + i * NT;         // 4096 float4 per matrix
        ((float4*)w1s)[idx] = ((const float4*)W1)[idx];
        ((float4*)w2s)[idx] = ((const float4*)W2)[idx];
    }
    #pragma unroll
    for (int i = 0; i < 2; i++) {       // W3 slice: 1024 float4
        int idx = tid + i * NT;
        int k = idx >> 3, cq = idx & 7;
        *(float4*)(w3s + k * 32 + cq * 4) =
            *(const float4*)(W3 + k * 4096 + r * 32 + cq * 4);
    }
    if (tid < 128) { b1s[tid] = b1[tid]; b2s[tid] = b2[tid]; }

    // z0 = X(0) @ Wi + bi
    if (tid < 128) {
        const float* ca = coeffs + (size_t)r * 8192;
        float acc = bi[tid];
        #pragma unroll
        for (int c = 0; c < 32; c++)
            acc = fmaf(ca[c], Wi[c * 128 + tid], acc);
        zs[tid] = acc; ys[tid] = acc; kacc[tid] = 0.0f;
    }
    __syncthreads();

    const unsigned int base = *sbase;
    unsigned int bno = 0;

    // per-thread GEMM constants: 2 rows x 4 cols
    const int cg = tid & 7, rg = tid >> 3;
    const int r0 = rg << 1;
    const float4 b3q = *(const float4*)(b3 + r * 32 + (cg << 2));
    u64 B01, B23;
    asm("mov.b64 %0, {%1,%2};" : "=l"(B01) : "f"(b3q.x), "f"(b3q.y));
    asm("mov.b64 %0, {%1,%2};" : "=l"(B23) : "f"(b3q.z), "f"(b3q.w));
    const float* hg = g_h2T + r0;           // global h stream base
    const float* ws = w3s + (cg << 2);      // smem w base

    for (int s = 0; s < 64; s++) {
        // publish dX for this segment (f=0, f=0.5, f=1)
        if (tid < 32) {
            const float* base_c = coeffs + (size_t)r * 8192 + s * 128;
            int c = tid;
            float cb = base_c[32 + c], c2 = base_c[64 + c], c3 = base_c[96 + c];
            g_dx[(r * 3 + 0) * 32 + c] = cb;
            g_dx[(r * 3 + 1) * 32 + c] = fmaf(0.25f, c3, fmaf(0.5f, c2, cb));
            g_dx[(r * 3 + 2) * 32 + c] = (s < 63) ? base_c[128 + 32 + c]
                                                  : (cb + c2 + c3);
        }

        for (int stage = 0; stage < 4; stage++) {
            // ---- row-owner: layers 1,2 on own row, publish h2 ----
            gemv128(ys,  w1s, b1s, h1s,   sp);
            gemv128(h1s, w2s, b2s, h2row, sp);
            if (tid < 128)
                g_h2T[tid * 128 + r] = h2row[tid];

            grid_barrier(base + (++bno));   // A: all h2 rows + dX published

            // dX loads hoisted: L2 latency hides under the GEMM
            const int sel = (stage == 0) ? 0 : ((stage == 3) ? 2 : 1);
            float4 dA = *(const float4*)(g_dx + (r0 * 3 + sel) * 32 + (cg << 2));
            float4 dB = *(const float4*)(g_dx + ((r0 + 1) * 3 + sel) * 32 + (cg << 2));

            // ---- GEMM: h streamed from global (reg double-buffer), w smem ----
            u64 A01 = B01, A23 = B23;   // row r0,   cols (0,1) (2,3)
            u64 E01 = B01, E23 = B23;   // row r0+1
            {
                float2 hb0[8], hb1[8];
                #pragma unroll
                for (int kk = 0; kk < 8; kk++)
                    hb0[kk] = *(const float2*)(hg + kk * 128);
                #pragma unroll 2
                for (int blk = 0; blk < 16; blk++) {
                    float2* cur = (blk & 1) ? hb1 : hb0;
                    float2* nxt = (blk & 1) ? hb0 : hb1;
                    const float* hnx = hg + (blk + 1) * 1024;
                    const float* wb  = ws + blk * 256;
                    #pragma unroll
                    for (int kk = 0; kk < 8; kk++) {
                        if (blk < 15)
                            nxt[kk] = *(const float2*)(hnx + kk * 128);
                        float2 h = cur[kk];
                        float4 w = *(const float4*)(wb + kk * 32);
                        u64 w01, w23, hx2, hy2;
                        asm("mov.b64 %0, {%1,%2};" : "=l"(w01) : "f"(w.x), "f"(w.y));
                        asm("mov.b64 %0, {%1,%2};" : "=l"(w23) : "f"(w.z), "f"(w.w));
                        asm("mov.b64 %0, {%1,%1};" : "=l"(hx2) : "f"(h.x));
                        asm("mov.b64 %0, {%1,%1};" : "=l"(hy2) : "f"(h.y));
                        asm("fma.rn.f32x2 %0,%1,%2,%0;" : "+l"(A01) : "l"(w01), "l"(hx2));
                        asm("fma.rn.f32x2 %0,%1,%2,%0;" : "+l"(A23) : "l"(w23), "l"(hx2));
                        asm("fma.rn.f32x2 %0,%1,%2,%0;" : "+l"(E01) : "l"(w01), "l"(hy2));
                        asm("fma.rn.f32x2 %0,%1,%2,%0;" : "+l"(E23) : "l"(w23), "l"(hy2));
                    }
                }
            }
            float a0, a1, a2, a3, e0, e1, e2, e3;
            asm("mov.b64 {%0,%1}, %2;" : "=f"(a0), "=f"(a1) : "l"(A01));
            asm("mov.b64 {%0,%1}, %2;" : "=f"(a2), "=f"(a3) : "l"(A23));
            asm("mov.b64 {%0,%1}, %2;" : "=f"(e0), "=f"(e1) : "l"(E01));
            asm("mov.b64 {%0,%1}, %2;" : "=f"(e2), "=f"(e3) : "l"(E23));

            // ---- tanh (rational, batched rcp) + contraction with dX ----
            float p[8], q[8], inv[8];
            p[0] = tanh_pq(a0, q[0]); p[1] = tanh_pq(a1, q[1]);
            p[2] = tanh_pq(a2, q[2]); p[3] = tanh_pq(a3, q[3]);
            p[4] = tanh_pq(e0, q[4]); p[5] = tanh_pq(e1, q[5]);
            p[6] = tanh_pq(e2, q[6]); p[7] = tanh_pq(e3, q[7]);
            rcp4(q,     inv);
            rcp4(q + 4, inv + 4);

            float pr0 = p[0]*inv[0]*dA.x + p[1]*inv[1]*dA.y
                      + p[2]*inv[2]*dA.z + p[3]*inv[3]*dA.w;
            float pr1 = p[4]*inv[4]*dB.x + p[5]*inv[5]*dB.y
                      + p[6]*inv[6]*dB.z + p[7]*inv[7]*dB.w;
            #pragma unroll
            for (int off = 4; off >= 1; off >>= 1) {
                pr0 += __shfl_down_sync(0xffffffffu, pr0, off);
                pr1 += __shfl_down_sync(0xffffffffu, pr1, off);
            }
            if (cg == 0) {
                g_dz[ r0      * 128 + r] = pr0;
                g_dz[(r0 + 1) * 128 + r] = pr1;
            }

            grid_barrier(base + (++bno));   // B: dz complete

            // ---- row-owner: RK4 stage update ----
            if (tid < 32) {
                int h0 = tid << 2;
                float4 dz = *(const float4*)(g_dz + r * 128 + h0);
                float4 kq = *(float4*)(kacc + h0);
                float4 zq = *(float4*)(zs + h0);
                float kw = (stage == 0 || stage == 3) ? 1.0f : 2.0f;
                kq.x = fmaf(kw, dz.x, kq.x); kq.y = fmaf(kw, dz.y, kq.y);
                kq.z = fmaf(kw, dz.z, kq.z); kq.w = fmaf(kw, dz.w, kq.w);
                if (stage < 3) {
                    float aa = (stage == 2) ? 1.0f : 0.5f;
                    float4 yq;
                    yq.x = fmaf(aa, dz.x, zq.x); yq.y = fmaf(aa, dz.y, zq.y);
                    yq.z = fmaf(aa, dz.z, zq.z); yq.w = fmaf(aa, dz.w, zq.w);
                    *(float4*)(ys + h0) = yq;
                    *(float4*)(kacc + h0) = kq;
                } else {
                    const float c6 = 1.0f / 6.0f;
                    zq.x = fmaf(c6, kq.x, zq.x); zq.y = fmaf(c6, kq.y, zq.y);
                    zq.z = fmaf(c6, kq.z, zq.z); zq.w = fmaf(c6, kq.w, zq.w);
                    *(float4*)(zs + h0) = zq;
                    *(float4*)(ys + h0) = zq;
                    *(float4*)(kacc + h0) = make_float4(0.f, 0.f, 0.f, 0.f);
                }
            }
            __syncthreads();
        }
    }

    // ---- readout: out[r] = sigmoid(z @ Wr + br) ----
    if (tid < 32) {
        float part = 0.0f;
        #pragma unroll
        for (int h = tid; h < 128; h += 32)
            part = fmaf(zs[h], Wr[h], part);
        #pragma unroll
        for (int off = 16; off >= 1; off >>= 1)
            part += __shfl_down_sync(0xffffffffu, part, off);
        if (tid == 0)
            out[r] = 1.0f / (1.0f + __expf(-(part + br[0])));
    }
}

extern "C" void kernel_launch(void* const* d_in, const int* in_sizes, int n_in,
                              void* d_out, int out_size)
{
    const float* coeffs = (const float*)d_in[0];
    const float* W1 = (const float*)d_in[1];
    const float* b1 = (const float*)d_in[2];
    const float* W2 = (const float*)d_in[3];
    const float* b2 = (const float*)d_in[4];
    const float* W3 = (const float*)d_in[5];
    const float* b3 = (const float*)d_in[6];
    const float* Wi = (const float*)d_in[7];
    const float* bi = (const float*)d_in[8];
    const float* Wr = (const float*)d_in[9];
    const float* br = (const float*)d_in[10];
    float* out = (float*)d_out;

    cudaFuncSetAttribute(cde_kernel,
                         cudaFuncAttributeMaxDynamicSharedMemorySize, SMEM_BYTES);
    cde_kernel<<<NCTAS, NT, SMEM_BYTES>>>(coeffs, W1, b1, W2, b2, W3, b3,
                                          Wi, bi, Wr, br, out);
}